// round 11
// baseline (speedup 1.0000x reference)
#include <cuda_runtime.h>
#include <math.h>

#define BGR 32768
#define NPG 54
#define EPG 144
#define GLOB 10
#define F0 8
#define F1 16
#define F2 4
#define CAT 226   /* 54*4 + 10 */
#define H1 128
#define BM 64

// Scratch: concat([embeds, g]) per graph, [B, 226]
__device__ float g_emb[BGR * CAT];

// per-graph named barrier (two graphs per CTA, 128 threads each)
#define GSYNC() asm volatile("bar.sync %0, 128;" :: "r"(sub + 1) : "memory")

// ---------------------------------------------------------------------------
// Kernel 1: per-graph GraphConv x2 (+ ReLU) and the global-feature MLP.
// TWO graphs per CTA (256 threads). __launch_bounds__(256,4) caps regs at 64
// so 4 CTAs fit per SM (regfile was the binding constraint). Weights are
// read from smem in the inner loops (broadcast LDS) instead of register
// arrays. Named barriers decouple the two graphs' phases.
// ---------------------------------------------------------------------------
__global__ void __launch_bounds__(256, 4) gconv_kernel(
    const float* __restrict__ x,
    const int*   __restrict__ eidx,    // [2, E]
    const float* __restrict__ eattr,
    const float* __restrict__ gfeat,
    const float* __restrict__ W_rel1, const float* __restrict__ b1,
    const float* __restrict__ W_root1,
    const float* __restrict__ W_rel2, const float* __restrict__ b2,
    const float* __restrict__ W_root2,
    const float* __restrict__ Wg1, const float* __restrict__ bg1,
    const float* __restrict__ Wg2, const float* __restrict__ bg2,
    const float* __restrict__ Wg3, const float* __restrict__ bg3)
{
    const int tid = threadIdx.x;
    const int sub = tid >> 7;          // which of the 2 graphs
    const int lt  = tid & 127;         // lane within the graph's 128 threads
    const int b   = blockIdx.x * 2 + sub;

    __shared__ float4 sx4[2][NPG * 2];     // x        [54][8]  as float4 pairs
    __shared__ float4 sh4[2][NPG * 4];     // conv1 out [54][16]
    __shared__ float4 sagg4[2][NPG * 4];   // agg scratch (aliased early)
    __shared__ float2 sedge[2][EPG];       // dst-sorted {attr, src_as_float}
    __shared__ int    soff[2][NPG + 1];
    __shared__ int    scur[2][NPG];
    __shared__ int    wsum0[2];
    __shared__ float  wr1[F0 * F1], wrt1[F0 * F1], sb1[F1];
    __shared__ float  wr2[F1 * F2], wrt2[F1 * F2], sb2[F2];
    __shared__ float  wg1[GLOB * 8], wg2[64], wg3[80];
    __shared__ float  sbg1[8], sbg2[8], sbg3[GLOB];
    __shared__ float  sgf[2][GLOB], sg1[2][8], sg2[2][8];

    // unsorted edge staging aliases this graph's sagg4 (dead until after scatter)
    float* sattr_u = (float*)sagg4[sub];       // [144]
    short* ssrc_u  = (short*)(sattr_u + EPG);  // [144]
    short* sdst_u  = ssrc_u + EPG;             // [144]
    float* shf     = (float*)sh4[sub];

    // ---- loads ----
    {
        const float4* xg = (const float4*)(x + (size_t)b * (NPG * F0));
        if (lt < NPG * 2) sx4[sub][lt] = xg[lt];
    }
    {
        const int*   srcg = eidx + (size_t)b * EPG;
        const int*   dstg = eidx + (size_t)BGR * EPG + (size_t)b * EPG;
        const float* ag   = eattr + (size_t)b * EPG;
        const int base = b * NPG;
        for (int e = lt; e < EPG; e += 128) {
            ssrc_u[e]  = (short)(srcg[e] - base);
            sdst_u[e]  = (short)(dstg[e] - base);
            sattr_u[e] = ag[e];
        }
    }
    // weights: one copy, loaded by the whole CTA
    if (tid < F0 * F1) { wr1[tid] = W_rel1[tid]; wrt1[tid] = W_root1[tid]; }
    if (tid >= 128 && tid < 128 + F1 * F2) {
        int i = tid - 128; wr2[i] = W_rel2[i]; wrt2[i] = W_root2[i];
    }
    if (tid >= 192 && tid < 192 + F1) sb1[tid - 192] = b1[tid - 192];
    if (tid >= 208 && tid < 208 + F2) sb2[tid - 208] = b2[tid - 208];
    if (tid < GLOB * 8) wg1[tid] = Wg1[tid];
    if (tid >= 80 && tid < 144) wg2[tid - 80] = Wg2[tid - 80];
    if (tid >= 144 && tid < 224) wg3[tid - 144] = Wg3[tid - 144];
    if (tid >= 224 && tid < 232) sbg1[tid - 224] = bg1[tid - 224];
    if (tid >= 232 && tid < 240) sbg2[tid - 232] = bg2[tid - 232];
    if (tid >= 240 && tid < 250) sbg3[tid - 240] = bg3[tid - 240];
    if (lt < GLOB) sgf[sub][lt] = gfeat[(size_t)b * GLOB + lt];
    if (lt < NPG) scur[sub][lt] = 0;
    __syncthreads();                 // the ONE full-CTA barrier (weights ready)

    // ---- degree counts (+ global-MLP layer 1) ----
    for (int e = lt; e < EPG; e += 128) atomicAdd(&scur[sub][sdst_u[e]], 1);
    if (lt < 8) {
        float v = sbg1[lt];
        #pragma unroll
        for (int i = 0; i < GLOB; i++) v += sgf[sub][i] * wg1[i * 8 + lt];
        sg1[sub][lt] = fmaxf(v, 0.f);
    }
    GSYNC();

    // ---- warp-shuffle prefix scan over 54 counts (2 warps per graph) ----
    if (lt < 64) {
        int c = (lt < NPG) ? scur[sub][lt] : 0;
        int lane = lt & 31;
        int v = c;
        #pragma unroll
        for (int o = 1; o < 32; o <<= 1) {
            int u = __shfl_up_sync(0xffffffffu, v, o);
            if (lane >= o) v += u;
        }
        if (lt < NPG) soff[sub][lt + 1] = v;
        if (lt == 31) wsum0[sub] = v;
        if (lt == 0)  soff[sub][0] = 0;
    }
    if (lt >= 64 && lt < 72) {     // global-MLP layer 2 on the third warp
        int j = lt - 64;
        float v = sbg2[j];
        #pragma unroll
        for (int i = 0; i < 8; i++) v += sg1[sub][i] * wg2[i * 8 + j];
        sg2[sub][j] = fmaxf(v, 0.f);
    }
    GSYNC();
    if (lt >= 32 && lt < NPG) soff[sub][lt + 1] += wsum0[sub];
    GSYNC();
    if (lt < NPG) scur[sub][lt] = soff[sub][lt];
    GSYNC();

    // ---- scatter edges into CSR slots (+ global-MLP layer 3 writeout) ----
    for (int e = lt; e < EPG; e += 128) {
        int slot = atomicAdd(&scur[sub][sdst_u[e]], 1);
        float2 pe; pe.x = sattr_u[e]; pe.y = __int_as_float((int)ssrc_u[e]);
        sedge[sub][slot] = pe;
    }
    if (lt < GLOB) {
        float v = sbg3[lt];
        #pragma unroll
        for (int i = 0; i < 8; i++) v += sg2[sub][i] * wg3[i * GLOB + lt];
        g_emb[(size_t)b * CAT + NPG * F2 + lt] = fmaxf(v, 0.f);
    }
    GSYNC();   // staging alias dead after this -> sagg4 reusable

    // ---- conv1 aggregation: one thread per (node, float4-half) ----
    if (lt < NPG * 2) {
        int n = lt >> 1, h = lt & 1;
        float4 a = make_float4(0.f, 0.f, 0.f, 0.f);
        int k1 = soff[sub][n + 1];
        for (int k = soff[sub][n]; k < k1; k++) {
            float2 e = sedge[sub][k];
            float4 xv = sx4[sub][__float_as_int(e.y) * 2 + h];
            a.x += e.x * xv.x; a.y += e.x * xv.y;
            a.z += e.x * xv.z; a.w += e.x * xv.w;
        }
        sagg4[sub][lt] = a;    // layout [n][2]
    }
    GSYNC();

    // ---- conv1 linear + ReLU: weights read from smem (broadcast LDS) ----
    {
        const int j = lt & 15, g = lt >> 4;   // g in 0..7
        const float bj = sb1[j];
        for (int n = g; n < NPG; n += 8) {
            float4 a0 = sagg4[sub][n * 2], a1 = sagg4[sub][n * 2 + 1];
            float4 x0 = sx4[sub][n * 2],  x1 = sx4[sub][n * 2 + 1];
            float v = bj;
            v += a0.x * wr1[0 * F1 + j] + a0.y * wr1[1 * F1 + j]
               + a0.z * wr1[2 * F1 + j] + a0.w * wr1[3 * F1 + j];
            v += a1.x * wr1[4 * F1 + j] + a1.y * wr1[5 * F1 + j]
               + a1.z * wr1[6 * F1 + j] + a1.w * wr1[7 * F1 + j];
            v += x0.x * wrt1[0 * F1 + j] + x0.y * wrt1[1 * F1 + j]
               + x0.z * wrt1[2 * F1 + j] + x0.w * wrt1[3 * F1 + j];
            v += x1.x * wrt1[4 * F1 + j] + x1.y * wrt1[5 * F1 + j]
               + x1.z * wrt1[6 * F1 + j] + x1.w * wrt1[7 * F1 + j];
            shf[n * F1 + j] = fmaxf(v, 0.f);
        }
    }
    GSYNC();

    // ---- conv2 aggregation: one thread per (node, float4-quarter) ----
    for (int it = lt; it < NPG * 4; it += 128) {
        int n = it >> 2, q = it & 3;
        float4 a = make_float4(0.f, 0.f, 0.f, 0.f);
        int k1 = soff[sub][n + 1];
        for (int k = soff[sub][n]; k < k1; k++) {
            float2 e = sedge[sub][k];
            float4 hv = sh4[sub][__float_as_int(e.y) * 4 + q];
            a.x += e.x * hv.x; a.y += e.x * hv.y;
            a.z += e.x * hv.z; a.w += e.x * hv.w;
        }
        sagg4[sub][it] = a;     // layout [n][4]
    }
    GSYNC();

    // ---- conv2 linear + ReLU, weights from smem, coalesced STG ----
    {
        const int c = lt & 3, g = lt >> 2;    // g in 0..31
        const float bc = sb2[c];
        for (int n = g; n < NPG; n += 32) {
            float v = bc;
            #pragma unroll
            for (int q = 0; q < 4; q++) {
                float4 a = sagg4[sub][n * 4 + q];
                float4 h = sh4[sub][n * 4 + q];
                v += a.x * wr2[(q * 4 + 0) * F2 + c] + a.y * wr2[(q * 4 + 1) * F2 + c]
                   + a.z * wr2[(q * 4 + 2) * F2 + c] + a.w * wr2[(q * 4 + 3) * F2 + c];
                v += h.x * wrt2[(q * 4 + 0) * F2 + c] + h.y * wrt2[(q * 4 + 1) * F2 + c]
                   + h.z * wrt2[(q * 4 + 2) * F2 + c] + h.w * wrt2[(q * 4 + 3) * F2 + c];
            }
            g_emb[(size_t)b * CAT + n * F2 + c] = fmaxf(v, 0.f);
        }
    }
}

// ---------------------------------------------------------------------------
// Kernel 2: head.  out = sigmoid( relu(concat @ Wo1 + bo1) @ Wo2 + bo2 )
// 64x128 tile, 128 threads, 8x8 microtile — measured at ~91% of the scalar
// FFMA roofline (fma pipe 45.4% of a 50%-max metric). Unchanged.
// ---------------------------------------------------------------------------
__global__ void __launch_bounds__(128) head_kernel(
    const float* __restrict__ Wo1, const float* __restrict__ bo1,
    const float* __restrict__ Wo2, const float* __restrict__ bo2,
    float* __restrict__ out)
{
    constexpr int BK = 16;
    __shared__ __align__(16) float  As[BK][BM + 4];   // padded, float4-readable
    __shared__ __align__(16) float4 Bs4[BK][32];      // [BK][128] floats
    __shared__ float  red[BM][17];

    const int rowBase = blockIdx.x * BM;
    const int tid = threadIdx.x;
    const int tx = tid & 15, ty = tid >> 4;           // ty 0..7

    float acc[8][8];
    #pragma unroll
    for (int i = 0; i < 8; i++)
        #pragma unroll
        for (int j = 0; j < 8; j++) acc[i][j] = 0.f;

    const float* A = g_emb + (size_t)rowBase * CAT;

    for (int k0 = 0; k0 < CAT; k0 += BK) {
        #pragma unroll
        for (int l = 0; l < 8; l++) {                 // A: 64x16 scalars
            int idx = tid + l * 128;
            int row = idx >> 4, kk = idx & 15;
            int k = k0 + kk;
            As[kk][row] = (k < CAT) ? A[(size_t)row * CAT + k] : 0.f;
        }
        #pragma unroll
        for (int l = 0; l < 4; l++) {                 // B: 16x128 via float4
            int idx = tid + l * 128;
            int kk = idx >> 5, c4 = idx & 31;
            int k = k0 + kk;
            Bs4[kk][c4] = (k < CAT) ? *(const float4*)&Wo1[(size_t)k * H1 + c4 * 4]
                                    : make_float4(0.f, 0.f, 0.f, 0.f);
        }
        __syncthreads();
        #pragma unroll
        for (int kk = 0; kk < BK; kk++) {
            float4 a0 = *(const float4*)&As[kk][ty * 8];
            float4 a1 = *(const float4*)&As[kk][ty * 8 + 4];
            float4 b0 = Bs4[kk][tx * 2];
            float4 b1 = Bs4[kk][tx * 2 + 1];
            float av[8] = {a0.x, a0.y, a0.z, a0.w, a1.x, a1.y, a1.z, a1.w};
            float bv[8] = {b0.x, b0.y, b0.z, b0.w, b1.x, b1.y, b1.z, b1.w};
            #pragma unroll
            for (int i = 0; i < 8; i++)
                #pragma unroll
                for (int j = 0; j < 8; j++)
                    acc[i][j] += av[i] * bv[j];
        }
        __syncthreads();
    }

    // epilogue: bias + relu + dot(Wo2) partials, then cross-column reduce
    float bb[8], w2[8];
    #pragma unroll
    for (int j = 0; j < 8; j++) { bb[j] = bo1[tx * 8 + j]; w2[j] = Wo2[tx * 8 + j]; }
    #pragma unroll
    for (int i = 0; i < 8; i++) {
        float p = 0.f;
        #pragma unroll
        for (int j = 0; j < 8; j++) {
            float v = fmaxf(acc[i][j] + bb[j], 0.f);
            p += v * w2[j];
        }
        red[ty * 8 + i][tx] = p;
    }
    __syncthreads();
    if (tid < BM) {
        float s = bo2[0];
        #pragma unroll
        for (int t = 0; t < 16; t++) s += red[tid][t];
        out[rowBase + tid] = 1.f / (1.f + expf(-s));
    }
}

extern "C" void kernel_launch(void* const* d_in, const int* in_sizes, int n_in,
                              void* d_out, int out_size)
{
    const float* x       = (const float*)d_in[0];
    const int*   eidx    = (const int*)  d_in[1];
    const float* eattr   = (const float*)d_in[2];
    const float* gfeat   = (const float*)d_in[3];
    const float* W_rel1  = (const float*)d_in[4];
    const float* b1      = (const float*)d_in[5];
    const float* W_root1 = (const float*)d_in[6];
    const float* W_rel2  = (const float*)d_in[7];
    const float* b2      = (const float*)d_in[8];
    const float* W_root2 = (const float*)d_in[9];
    const float* Wg1     = (const float*)d_in[10];
    const float* bg1     = (const float*)d_in[11];
    const float* Wg2     = (const float*)d_in[12];
    const float* bg2     = (const float*)d_in[13];
    const float* Wg3     = (const float*)d_in[14];
    const float* bg3     = (const float*)d_in[15];
    const float* Wo1     = (const float*)d_in[16];
    const float* bo1     = (const float*)d_in[17];
    const float* Wo2     = (const float*)d_in[18];
    const float* bo2     = (const float*)d_in[19];
    float* out = (float*)d_out;

    gconv_kernel<<<BGR / 2, 256>>>(x, eidx, eattr, gfeat,
                                   W_rel1, b1, W_root1,
                                   W_rel2, b2, W_root2,
                                   Wg1, bg1, Wg2, bg2, Wg3, bg3);
    head_kernel<<<BGR / BM, 128>>>(Wo1, bo1, Wo2, bo2, out);
}

// round 12
// speedup vs baseline: 1.2268x; 1.2268x over previous
#include <cuda_runtime.h>
#include <math.h>

#define BGR 32768
#define NPG 54
#define EPG 144
#define GLOB 10
#define F0 8
#define F1 16
#define F2 4
#define CAT 226   /* 54*4 + 10 */
#define H1 128
#define BM 64
#define WPG 4     /* graphs (warps) per gconv CTA */

// Scratch: concat([embeds, g]) per graph, [B, 226]
__device__ float g_emb[BGR * CAT];

// ---------------------------------------------------------------------------
// Kernel 1: warp-per-graph GraphConv x2 (+ ReLU) + global MLP.
// One WARP owns one graph: all phases are warp-synchronous (__syncwarp only,
// zero bar.sync after the weight load), so there is no cross-warp straggler
// dead time and every warp is an independent latency-hiding unit.
// Counting-sort CSR (shfl pair-scan), float4 feature traffic, packed
// {attr,src} edges, register-resident linear-layer weights, shuffle-only
// global MLP.
// ---------------------------------------------------------------------------
__global__ void __launch_bounds__(128) gconv_kernel(
    const float* __restrict__ x,
    const int*   __restrict__ eidx,    // [2, E]
    const float* __restrict__ eattr,
    const float* __restrict__ gfeat,
    const float* __restrict__ W_rel1, const float* __restrict__ b1,
    const float* __restrict__ W_root1,
    const float* __restrict__ W_rel2, const float* __restrict__ b2,
    const float* __restrict__ W_root2,
    const float* __restrict__ Wg1, const float* __restrict__ bg1,
    const float* __restrict__ Wg2, const float* __restrict__ bg2,
    const float* __restrict__ Wg3, const float* __restrict__ bg3)
{
    const int tid  = threadIdx.x;
    const int w    = tid >> 5;         // warp slot = graph slot in CTA
    const int lane = tid & 31;
    const int b    = blockIdx.x * WPG + w;

    __shared__ float4 sx4[WPG][NPG * 2];     // x        [54][8]  as float4
    __shared__ float4 sh4[WPG][NPG * 4];     // conv1 out [54][16]
    __shared__ float4 sagg4[WPG][NPG * 4];   // agg scratch (staging aliased)
    __shared__ float2 sedge[WPG][EPG];       // dst-sorted {attr, src}
    __shared__ int    soff[WPG][NPG + 2];
    __shared__ int    scur[WPG][NPG];
    __shared__ float  wr1[F0 * F1], wrt1[F0 * F1], sb1[F1];
    __shared__ float  wr2[F1 * F2], wrt2[F1 * F2], sb2[F2];
    __shared__ float  wg1[GLOB * 8], wg2[64], wg3[80];
    __shared__ float  sbg1[8], sbg2[8], sbg3[GLOB];

    // unsorted edge staging aliases this graph's sagg4 (dead after scatter)
    float* sattr_u = (float*)sagg4[w];         // [144]
    short* ssrc_u  = (short*)(sattr_u + EPG);  // [144]
    short* sdst_u  = ssrc_u + EPG;             // [144]
    float* shfp    = (float*)sh4[w];

    // ---- CTA-cooperative weight load (one bar.sync total) ----
    if (tid < F0 * F1) { wr1[tid] = W_rel1[tid]; wrt1[tid] = W_root1[tid]; }
    if (tid < F1 * F2) { wr2[tid] = W_rel2[tid]; wrt2[tid] = W_root2[tid]; }
    if (tid < F1) sb1[tid] = b1[tid];
    if (tid < F2) sb2[tid] = b2[tid];
    if (tid < GLOB * 8) wg1[tid] = Wg1[tid];
    if (tid < 64) wg2[tid] = Wg2[tid];
    if (tid < 80) wg3[tid] = Wg3[tid];
    if (tid < 8)  { sbg1[tid] = bg1[tid]; sbg2[tid] = bg2[tid]; }
    if (tid < GLOB) sbg3[tid] = bg3[tid];

    // ---- per-warp graph loads (start before the weight barrier resolves) ----
    {
        const float4* xg = (const float4*)(x + (size_t)b * (NPG * F0));
        #pragma unroll
        for (int i = lane; i < NPG * 2; i += 32) sx4[w][i] = xg[i];
    }
    {
        const int*   srcg = eidx + (size_t)b * EPG;
        const int*   dstg = eidx + (size_t)BGR * EPG + (size_t)b * EPG;
        const float* ag   = eattr + (size_t)b * EPG;
        const int base = b * NPG;
        #pragma unroll
        for (int e = lane; e < EPG; e += 32) {
            sattr_u[e] = ag[e];
            ssrc_u[e]  = (short)(srcg[e] - base);
            sdst_u[e]  = (short)(dstg[e] - base);
        }
    }
    for (int i = lane; i < NPG; i += 32) scur[w][i] = 0;
    __syncthreads();                       // weights + own-graph staging ready

    // ---- degree counts (warp-local smem atomics) ----
    #pragma unroll
    for (int e = lane; e < EPG; e += 32) atomicAdd(&scur[w][sdst_u[e]], 1);
    __syncwarp();

    // ---- pair-wise shfl prefix scan over 54 counts ----
    {
        int c0 = 0, c1 = 0;
        if (lane < 27) { c0 = scur[w][2 * lane]; c1 = scur[w][2 * lane + 1]; }
        int s = c0 + c1, incl = s;
        #pragma unroll
        for (int o = 1; o < 32; o <<= 1) {
            int u = __shfl_up_sync(0xffffffffu, incl, o);
            if (lane >= o) incl += u;
        }
        int excl = incl - s;
        if (lane < 27) { soff[w][2 * lane] = excl; soff[w][2 * lane + 1] = excl + c0; }
        if (lane == 26) soff[w][NPG] = incl;       // = EPG
    }
    __syncwarp();
    for (int i = lane; i < NPG; i += 32) scur[w][i] = soff[w][i];
    __syncwarp();

    // ---- scatter edges into CSR slots ----
    #pragma unroll
    for (int e = lane; e < EPG; e += 32) {
        int slot = atomicAdd(&scur[w][sdst_u[e]], 1);
        float2 pe; pe.x = sattr_u[e]; pe.y = __int_as_float((int)ssrc_u[e]);
        sedge[w][slot] = pe;
    }

    // ---- global MLP, pure shuffles (runs while scatter drains) ----
    {
        float gv = (lane < GLOB) ? gfeat[(size_t)b * GLOB + lane] : 0.f;
        float v1 = (lane < 8) ? sbg1[lane] : 0.f;
        #pragma unroll
        for (int i = 0; i < GLOB; i++) {
            float gi = __shfl_sync(0xffffffffu, gv, i);
            if (lane < 8) v1 += gi * wg1[i * 8 + lane];
        }
        v1 = fmaxf(v1, 0.f);
        float v2 = (lane < 8) ? sbg2[lane] : 0.f;
        #pragma unroll
        for (int i = 0; i < 8; i++) {
            float vi = __shfl_sync(0xffffffffu, v1, i);
            if (lane < 8) v2 += vi * wg2[i * 8 + lane];
        }
        v2 = fmaxf(v2, 0.f);
        float v3 = (lane < GLOB) ? sbg3[lane] : 0.f;
        #pragma unroll
        for (int i = 0; i < 8; i++) {
            float vi = __shfl_sync(0xffffffffu, v2, i);
            if (lane < GLOB) v3 += vi * wg3[i * GLOB + lane];
        }
        if (lane < GLOB)
            g_emb[(size_t)b * CAT + NPG * F2 + lane] = fmaxf(v3, 0.f);
    }
    __syncwarp();     // sedge complete; staging (sagg4 alias) now dead

    // ---- conv1 aggregation: lane strides over (node, float4-half) ----
    #pragma unroll
    for (int it = lane; it < NPG * 2; it += 32) {
        int n = it >> 1, h = it & 1;
        float4 a = make_float4(0.f, 0.f, 0.f, 0.f);
        int k1 = soff[w][n + 1];
        for (int k = soff[w][n]; k < k1; k++) {
            float2 e = sedge[w][k];
            float4 xv = sx4[w][__float_as_int(e.y) * 2 + h];
            a.x += e.x * xv.x; a.y += e.x * xv.y;
            a.z += e.x * xv.z; a.w += e.x * xv.w;
        }
        sagg4[w][it] = a;          // layout [n][2]
    }
    __syncwarp();

    // ---- conv1 linear + ReLU: 16 cols x 2 n-groups, weights in regs ----
    {
        const int j = lane & 15, g2 = lane >> 4;    // g2 in 0..1
        float wc[16];
        const float bj = sb1[j];
        #pragma unroll
        for (int i = 0; i < F0; i++) { wc[i] = wr1[i * F1 + j]; wc[8 + i] = wrt1[i * F1 + j]; }
        for (int n = g2; n < NPG; n += 2) {
            float4 a0 = sagg4[w][n * 2], a1 = sagg4[w][n * 2 + 1];
            float4 x0 = sx4[w][n * 2],  x1 = sx4[w][n * 2 + 1];
            float v = bj;
            v += a0.x * wc[0] + a0.y * wc[1] + a0.z * wc[2] + a0.w * wc[3];
            v += a1.x * wc[4] + a1.y * wc[5] + a1.z * wc[6] + a1.w * wc[7];
            v += x0.x * wc[8] + x0.y * wc[9] + x0.z * wc[10] + x0.w * wc[11];
            v += x1.x * wc[12] + x1.y * wc[13] + x1.z * wc[14] + x1.w * wc[15];
            shfp[n * F1 + j] = fmaxf(v, 0.f);
        }
    }
    __syncwarp();

    // ---- conv2 aggregation: lane strides over (node, float4-quarter) ----
    #pragma unroll
    for (int it = lane; it < NPG * 4; it += 32) {
        int n = it >> 2, q = it & 3;
        float4 a = make_float4(0.f, 0.f, 0.f, 0.f);
        int k1 = soff[w][n + 1];
        for (int k = soff[w][n]; k < k1; k++) {
            float2 e = sedge[w][k];
            float4 hv = sh4[w][__float_as_int(e.y) * 4 + q];
            a.x += e.x * hv.x; a.y += e.x * hv.y;
            a.z += e.x * hv.z; a.w += e.x * hv.w;
        }
        sagg4[w][it] = a;          // layout [n][4]
    }
    __syncwarp();

    // ---- conv2 linear + ReLU: 4 cols x 8 n-groups, coalesced STG ----
    {
        const int c = lane & 3, g2 = lane >> 2;     // g2 in 0..7
        float wa[16], wb[16];
        #pragma unroll
        for (int j = 0; j < F1; j++) { wa[j] = wr2[j * F2 + c]; wb[j] = wrt2[j * F2 + c]; }
        const float bc = sb2[c];
        for (int n = g2; n < NPG; n += 8) {
            float v = bc;
            #pragma unroll
            for (int q = 0; q < 4; q++) {
                float4 a = sagg4[w][n * 4 + q];
                float4 h = sh4[w][n * 4 + q];
                v += a.x * wa[q * 4 + 0] + a.y * wa[q * 4 + 1]
                   + a.z * wa[q * 4 + 2] + a.w * wa[q * 4 + 3];
                v += h.x * wb[q * 4 + 0] + h.y * wb[q * 4 + 1]
                   + h.z * wb[q * 4 + 2] + h.w * wb[q * 4 + 3];
            }
            g_emb[(size_t)b * CAT + n * F2 + c] = fmaxf(v, 0.f);
        }
    }
}

// ---------------------------------------------------------------------------
// Kernel 2: head.  out = sigmoid( relu(concat @ Wo1 + bo1) @ Wo2 + bo2 )
// 64x128 tile, 128 threads, 8x8 microtile — measured ~91% of the scalar
// FFMA roofline. Unchanged.
// ---------------------------------------------------------------------------
__global__ void __launch_bounds__(128) head_kernel(
    const float* __restrict__ Wo1, const float* __restrict__ bo1,
    const float* __restrict__ Wo2, const float* __restrict__ bo2,
    float* __restrict__ out)
{
    constexpr int BK = 16;
    __shared__ __align__(16) float  As[BK][BM + 4];   // padded, float4-readable
    __shared__ __align__(16) float4 Bs4[BK][32];      // [BK][128] floats
    __shared__ float  red[BM][17];

    const int rowBase = blockIdx.x * BM;
    const int tid = threadIdx.x;
    const int tx = tid & 15, ty = tid >> 4;           // ty 0..7

    float acc[8][8];
    #pragma unroll
    for (int i = 0; i < 8; i++)
        #pragma unroll
        for (int j = 0; j < 8; j++) acc[i][j] = 0.f;

    const float* A = g_emb + (size_t)rowBase * CAT;

    for (int k0 = 0; k0 < CAT; k0 += BK) {
        #pragma unroll
        for (int l = 0; l < 8; l++) {                 // A: 64x16 scalars
            int idx = tid + l * 128;
            int row = idx >> 4, kk = idx & 15;
            int k = k0 + kk;
            As[kk][row] = (k < CAT) ? A[(size_t)row * CAT + k] : 0.f;
        }
        #pragma unroll
        for (int l = 0; l < 4; l++) {                 // B: 16x128 via float4
            int idx = tid + l * 128;
            int kk = idx >> 5, c4 = idx & 31;
            int k = k0 + kk;
            Bs4[kk][c4] = (k < CAT) ? *(const float4*)&Wo1[(size_t)k * H1 + c4 * 4]
                                    : make_float4(0.f, 0.f, 0.f, 0.f);
        }
        __syncthreads();
        #pragma unroll
        for (int kk = 0; kk < BK; kk++) {
            float4 a0 = *(const float4*)&As[kk][ty * 8];
            float4 a1 = *(const float4*)&As[kk][ty * 8 + 4];
            float4 b0 = Bs4[kk][tx * 2];
            float4 b1 = Bs4[kk][tx * 2 + 1];
            float av[8] = {a0.x, a0.y, a0.z, a0.w, a1.x, a1.y, a1.z, a1.w};
            float bv[8] = {b0.x, b0.y, b0.z, b0.w, b1.x, b1.y, b1.z, b1.w};
            #pragma unroll
            for (int i = 0; i < 8; i++)
                #pragma unroll
                for (int j = 0; j < 8; j++)
                    acc[i][j] += av[i] * bv[j];
        }
        __syncthreads();
    }

    // epilogue: bias + relu + dot(Wo2) partials, then cross-column reduce
    float bb[8], w2[8];
    #pragma unroll
    for (int j = 0; j < 8; j++) { bb[j] = bo1[tx * 8 + j]; w2[j] = Wo2[tx * 8 + j]; }
    #pragma unroll
    for (int i = 0; i < 8; i++) {
        float p = 0.f;
        #pragma unroll
        for (int j = 0; j < 8; j++) {
            float v = fmaxf(acc[i][j] + bb[j], 0.f);
            p += v * w2[j];
        }
        red[ty * 8 + i][tx] = p;
    }
    __syncthreads();
    if (tid < BM) {
        float s = bo2[0];
        #pragma unroll
        for (int t = 0; t < 16; t++) s += red[tid][t];
        out[rowBase + tid] = 1.f / (1.f + expf(-s));
    }
}

extern "C" void kernel_launch(void* const* d_in, const int* in_sizes, int n_in,
                              void* d_out, int out_size)
{
    const float* x       = (const float*)d_in[0];
    const int*   eidx    = (const int*)  d_in[1];
    const float* eattr   = (const float*)d_in[2];
    const float* gfeat   = (const float*)d_in[3];
    const float* W_rel1  = (const float*)d_in[4];
    const float* b1      = (const float*)d_in[5];
    const float* W_root1 = (const float*)d_in[6];
    const float* W_rel2  = (const float*)d_in[7];
    const float* b2      = (const float*)d_in[8];
    const float* W_root2 = (const float*)d_in[9];
    const float* Wg1     = (const float*)d_in[10];
    const float* bg1     = (const float*)d_in[11];
    const float* Wg2     = (const float*)d_in[12];
    const float* bg2     = (const float*)d_in[13];
    const float* Wg3     = (const float*)d_in[14];
    const float* bg3     = (const float*)d_in[15];
    const float* Wo1     = (const float*)d_in[16];
    const float* bo1     = (const float*)d_in[17];
    const float* Wo2     = (const float*)d_in[18];
    const float* bo2     = (const float*)d_in[19];
    float* out = (float*)d_out;

    gconv_kernel<<<BGR / WPG, 128>>>(x, eidx, eattr, gfeat,
                                     W_rel1, b1, W_root1,
                                     W_rel2, b2, W_root2,
                                     Wg1, bg1, Wg2, bg2, Wg3, bg3);
    head_kernel<<<BGR / BM, 128>>>(Wo1, bo1, Wo2, bo2, out);
}

// round 13
// speedup vs baseline: 1.4480x; 1.1802x over previous
#include <cuda_runtime.h>
#include <math.h>

#define BGR 32768
#define NPG 54
#define EPG 144
#define GLOB 10
#define F0 8
#define F1 16
#define F2 4
#define CAT 226   /* 54*4 + 10 */
#define H1 128
#define BM 64
#define WPG 4     /* graphs (warps) per gconv CTA */

// Scratch: concat([embeds, g]) per graph, [B, 226]
__device__ float g_emb[BGR * CAT];

// ---------------------------------------------------------------------------
// Kernel 1: warp-per-graph GraphConv x2 (+ ReLU) + global MLP.
// One WARP owns one graph (all phases warp-synchronous, zero bar.sync after
// the weight load). conv1: aggregate(8-dim) -> linear.  conv2: TRANSFORM-
// FIRST -> aggregate 4-dim messages (lin_rel is linear, so it commutes with
// the weighted sum) — 4x fewer gather LDS + fused output store.
// ---------------------------------------------------------------------------
__global__ void __launch_bounds__(128) gconv_kernel(
    const float* __restrict__ x,
    const int*   __restrict__ eidx,    // [2, E]
    const float* __restrict__ eattr,
    const float* __restrict__ gfeat,
    const float* __restrict__ W_rel1, const float* __restrict__ b1,
    const float* __restrict__ W_root1,
    const float* __restrict__ W_rel2, const float* __restrict__ b2,
    const float* __restrict__ W_root2,
    const float* __restrict__ Wg1, const float* __restrict__ bg1,
    const float* __restrict__ Wg2, const float* __restrict__ bg2,
    const float* __restrict__ Wg3, const float* __restrict__ bg3)
{
    const int tid  = threadIdx.x;
    const int w    = tid >> 5;         // warp slot = graph slot in CTA
    const int lane = tid & 31;
    const int b    = blockIdx.x * WPG + w;

    __shared__ float4 sx4[WPG][NPG * 2];     // x        [54][8]  as float4
    __shared__ float4 sh4[WPG][NPG * 4];     // conv1 out [54][16]
    __shared__ float4 sagg4[WPG][NPG * 2];   // conv1 agg / conv2 {t, r}
    __shared__ float2 sedge[WPG][EPG];       // dst-sorted {attr, src}
    __shared__ int    soff[WPG][NPG + 2];
    __shared__ int    scur[WPG][NPG];
    __shared__ float  wr1[F0 * F1], wrt1[F0 * F1], sb1[F1];
    __shared__ float  wr2[F1 * F2], wrt2[F1 * F2], sb2[F2];
    __shared__ float  wg1[GLOB * 8], wg2[64], wg3[80];
    __shared__ float  sbg1[8], sbg2[8], sbg3[GLOB];

    // unsorted edge staging aliases this graph's sagg4 (dead after scatter;
    // needs 1152 B of the 1728 B region)
    float* sattr_u = (float*)sagg4[w];         // [144]
    short* ssrc_u  = (short*)(sattr_u + EPG);  // [144]
    short* sdst_u  = ssrc_u + EPG;             // [144]
    float* shfp    = (float*)sh4[w];

    // ---- CTA-cooperative weight load (one bar.sync total) ----
    if (tid < F0 * F1) { wr1[tid] = W_rel1[tid]; wrt1[tid] = W_root1[tid]; }
    if (tid < F1 * F2) { wr2[tid] = W_rel2[tid]; wrt2[tid] = W_root2[tid]; }
    if (tid < F1) sb1[tid] = b1[tid];
    if (tid < F2) sb2[tid] = b2[tid];
    if (tid < GLOB * 8) wg1[tid] = Wg1[tid];
    if (tid < 64) wg2[tid] = Wg2[tid];
    if (tid < 80) wg3[tid] = Wg3[tid];
    if (tid < 8)  { sbg1[tid] = bg1[tid]; sbg2[tid] = bg2[tid]; }
    if (tid < GLOB) sbg3[tid] = bg3[tid];

    // ---- per-warp graph loads ----
    {
        const float4* xg = (const float4*)(x + (size_t)b * (NPG * F0));
        #pragma unroll
        for (int i = lane; i < NPG * 2; i += 32) sx4[w][i] = xg[i];
    }
    {
        const int*   srcg = eidx + (size_t)b * EPG;
        const int*   dstg = eidx + (size_t)BGR * EPG + (size_t)b * EPG;
        const float* ag   = eattr + (size_t)b * EPG;
        const int base = b * NPG;
        #pragma unroll
        for (int e = lane; e < EPG; e += 32) {
            sattr_u[e] = ag[e];
            ssrc_u[e]  = (short)(srcg[e] - base);
            sdst_u[e]  = (short)(dstg[e] - base);
        }
    }
    for (int i = lane; i < NPG; i += 32) scur[w][i] = 0;
    __syncthreads();                       // weights + own-graph staging ready

    // ---- degree counts (warp-local smem atomics) ----
    #pragma unroll
    for (int e = lane; e < EPG; e += 32) atomicAdd(&scur[w][sdst_u[e]], 1);
    __syncwarp();

    // ---- pair-wise shfl prefix scan over 54 counts ----
    {
        int c0 = 0, c1 = 0;
        if (lane < 27) { c0 = scur[w][2 * lane]; c1 = scur[w][2 * lane + 1]; }
        int s = c0 + c1, incl = s;
        #pragma unroll
        for (int o = 1; o < 32; o <<= 1) {
            int u = __shfl_up_sync(0xffffffffu, incl, o);
            if (lane >= o) incl += u;
        }
        int excl = incl - s;
        if (lane < 27) { soff[w][2 * lane] = excl; soff[w][2 * lane + 1] = excl + c0; }
        if (lane == 26) soff[w][NPG] = incl;       // = EPG
    }
    __syncwarp();
    for (int i = lane; i < NPG; i += 32) scur[w][i] = soff[w][i];
    __syncwarp();

    // ---- scatter edges into CSR slots ----
    #pragma unroll
    for (int e = lane; e < EPG; e += 32) {
        int slot = atomicAdd(&scur[w][sdst_u[e]], 1);
        float2 pe; pe.x = sattr_u[e]; pe.y = __int_as_float((int)ssrc_u[e]);
        sedge[w][slot] = pe;
    }

    // ---- global MLP, pure shuffles (runs while scatter drains) ----
    {
        float gv = (lane < GLOB) ? gfeat[(size_t)b * GLOB + lane] : 0.f;
        float v1 = (lane < 8) ? sbg1[lane] : 0.f;
        #pragma unroll
        for (int i = 0; i < GLOB; i++) {
            float gi = __shfl_sync(0xffffffffu, gv, i);
            if (lane < 8) v1 += gi * wg1[i * 8 + lane];
        }
        v1 = fmaxf(v1, 0.f);
        float v2 = (lane < 8) ? sbg2[lane] : 0.f;
        #pragma unroll
        for (int i = 0; i < 8; i++) {
            float vi = __shfl_sync(0xffffffffu, v1, i);
            if (lane < 8) v2 += vi * wg2[i * 8 + lane];
        }
        v2 = fmaxf(v2, 0.f);
        float v3 = (lane < GLOB) ? sbg3[lane] : 0.f;
        #pragma unroll
        for (int i = 0; i < 8; i++) {
            float vi = __shfl_sync(0xffffffffu, v2, i);
            if (lane < GLOB) v3 += vi * wg3[i * GLOB + lane];
        }
        if (lane < GLOB)
            g_emb[(size_t)b * CAT + NPG * F2 + lane] = fmaxf(v3, 0.f);
    }
    __syncwarp();     // sedge complete; staging (sagg4 alias) now dead

    // ---- conv1 aggregation: lane strides over (node, float4-half) ----
    #pragma unroll
    for (int it = lane; it < NPG * 2; it += 32) {
        int n = it >> 1, h = it & 1;
        float4 a = make_float4(0.f, 0.f, 0.f, 0.f);
        int k1 = soff[w][n + 1];
        for (int k = soff[w][n]; k < k1; k++) {
            float2 e = sedge[w][k];
            float4 xv = sx4[w][__float_as_int(e.y) * 2 + h];
            a.x += e.x * xv.x; a.y += e.x * xv.y;
            a.z += e.x * xv.z; a.w += e.x * xv.w;
        }
        sagg4[w][it] = a;          // layout [n][2]
    }
    __syncwarp();

    // ---- conv1 linear + ReLU: 16 cols x 2 n-groups, weights in regs ----
    {
        const int j = lane & 15, g2 = lane >> 4;    // g2 in 0..1
        float wc[16];
        const float bj = sb1[j];
        #pragma unroll
        for (int i = 0; i < F0; i++) { wc[i] = wr1[i * F1 + j]; wc[8 + i] = wrt1[i * F1 + j]; }
        for (int n = g2; n < NPG; n += 2) {
            float4 a0 = sagg4[w][n * 2], a1 = sagg4[w][n * 2 + 1];
            float4 x0 = sx4[w][n * 2],  x1 = sx4[w][n * 2 + 1];
            float v = bj;
            v += a0.x * wc[0] + a0.y * wc[1] + a0.z * wc[2] + a0.w * wc[3];
            v += a1.x * wc[4] + a1.y * wc[5] + a1.z * wc[6] + a1.w * wc[7];
            v += x0.x * wc[8] + x0.y * wc[9] + x0.z * wc[10] + x0.w * wc[11];
            v += x1.x * wc[12] + x1.y * wc[13] + x1.z * wc[14] + x1.w * wc[15];
            shfp[n * F1 + j] = fmaxf(v, 0.f);
        }
    }
    __syncwarp();

    // ---- conv2 TRANSFORM-FIRST: t[n][c] = h_n @ Wrel2, r[n][c] = b2 + h_n @ Wroot2
    //      t -> sagg4[w][n], r -> sagg4[w][NPG + n]  (conv1 agg data is dead)
    {
        const int c = lane & 3, g2 = lane >> 2;     // g2 in 0..7
        float wa[16], wb[16];
        #pragma unroll
        for (int j = 0; j < F1; j++) { wa[j] = wr2[j * F2 + c]; wb[j] = wrt2[j * F2 + c]; }
        const float bc = sb2[c];
        for (int n = g2; n < NPG; n += 8) {
            float tr = 0.f, rr = bc;
            #pragma unroll
            for (int q = 0; q < 4; q++) {
                float4 h = sh4[w][n * 4 + q];
                tr += h.x * wa[q * 4 + 0] + h.y * wa[q * 4 + 1]
                    + h.z * wa[q * 4 + 2] + h.w * wa[q * 4 + 3];
                rr += h.x * wb[q * 4 + 0] + h.y * wb[q * 4 + 1]
                    + h.z * wb[q * 4 + 2] + h.w * wb[q * 4 + 3];
            }
            ((float*)&sagg4[w][n])[c]       = tr;
            ((float*)&sagg4[w][NPG + n])[c] = rr;
        }
    }
    __syncwarp();

    // ---- conv2 aggregate 4-dim messages + fused output store ----
    //      out[n] = relu( r[n] + sum_k w_k * t[src_k] )
    for (int n = lane; n < NPG; n += 32) {
        float4 a = make_float4(0.f, 0.f, 0.f, 0.f);
        int k1 = soff[w][n + 1];
        for (int k = soff[w][n]; k < k1; k++) {
            float2 e = sedge[w][k];
            float4 tv = sagg4[w][__float_as_int(e.y)];
            a.x += e.x * tv.x; a.y += e.x * tv.y;
            a.z += e.x * tv.z; a.w += e.x * tv.w;
        }
        float4 r = sagg4[w][NPG + n];
        float2 lo = make_float2(fmaxf(a.x + r.x, 0.f), fmaxf(a.y + r.y, 0.f));
        float2 hi = make_float2(fmaxf(a.z + r.z, 0.f), fmaxf(a.w + r.w, 0.f));
        // g_emb graph base is only 8B-aligned (CAT=226) -> two STG.64
        float* dst = g_emb + (size_t)b * CAT + n * F2;
        *(float2*)dst       = lo;
        *(float2*)(dst + 2) = hi;
    }
}

// ---------------------------------------------------------------------------
// Kernel 2: head.  out = sigmoid( relu(concat @ Wo1 + bo1) @ Wo2 + bo2 )
// 64x128 tile, 128 threads, 8x8 microtile — measured ~91% of the scalar
// FFMA roofline. Unchanged.
// ---------------------------------------------------------------------------
__global__ void __launch_bounds__(128) head_kernel(
    const float* __restrict__ Wo1, const float* __restrict__ bo1,
    const float* __restrict__ Wo2, const float* __restrict__ bo2,
    float* __restrict__ out)
{
    constexpr int BK = 16;
    __shared__ __align__(16) float  As[BK][BM + 4];   // padded, float4-readable
    __shared__ __align__(16) float4 Bs4[BK][32];      // [BK][128] floats
    __shared__ float  red[BM][17];

    const int rowBase = blockIdx.x * BM;
    const int tid = threadIdx.x;
    const int tx = tid & 15, ty = tid >> 4;           // ty 0..7

    float acc[8][8];
    #pragma unroll
    for (int i = 0; i < 8; i++)
        #pragma unroll
        for (int j = 0; j < 8; j++) acc[i][j] = 0.f;

    const float* A = g_emb + (size_t)rowBase * CAT;

    for (int k0 = 0; k0 < CAT; k0 += BK) {
        #pragma unroll
        for (int l = 0; l < 8; l++) {                 // A: 64x16 scalars
            int idx = tid + l * 128;
            int row = idx >> 4, kk = idx & 15;
            int k = k0 + kk;
            As[kk][row] = (k < CAT) ? A[(size_t)row * CAT + k] : 0.f;
        }
        #pragma unroll
        for (int l = 0; l < 4; l++) {                 // B: 16x128 via float4
            int idx = tid + l * 128;
            int kk = idx >> 5, c4 = idx & 31;
            int k = k0 + kk;
            Bs4[kk][c4] = (k < CAT) ? *(const float4*)&Wo1[(size_t)k * H1 + c4 * 4]
                                    : make_float4(0.f, 0.f, 0.f, 0.f);
        }
        __syncthreads();
        #pragma unroll
        for (int kk = 0; kk < BK; kk++) {
            float4 a0 = *(const float4*)&As[kk][ty * 8];
            float4 a1 = *(const float4*)&As[kk][ty * 8 + 4];
            float4 b0 = Bs4[kk][tx * 2];
            float4 b1 = Bs4[kk][tx * 2 + 1];
            float av[8] = {a0.x, a0.y, a0.z, a0.w, a1.x, a1.y, a1.z, a1.w};
            float bv[8] = {b0.x, b0.y, b0.z, b0.w, b1.x, b1.y, b1.z, b1.w};
            #pragma unroll
            for (int i = 0; i < 8; i++)
                #pragma unroll
                for (int j = 0; j < 8; j++)
                    acc[i][j] += av[i] * bv[j];
        }
        __syncthreads();
    }

    // epilogue: bias + relu + dot(Wo2) partials, then cross-column reduce
    float bb[8], w2[8];
    #pragma unroll
    for (int j = 0; j < 8; j++) { bb[j] = bo1[tx * 8 + j]; w2[j] = Wo2[tx * 8 + j]; }
    #pragma unroll
    for (int i = 0; i < 8; i++) {
        float p = 0.f;
        #pragma unroll
        for (int j = 0; j < 8; j++) {
            float v = fmaxf(acc[i][j] + bb[j], 0.f);
            p += v * w2[j];
        }
        red[ty * 8 + i][tx] = p;
    }
    __syncthreads();
    if (tid < BM) {
        float s = bo2[0];
        #pragma unroll
        for (int t = 0; t < 16; t++) s += red[tid][t];
        out[rowBase + tid] = 1.f / (1.f + expf(-s));
    }
}

extern "C" void kernel_launch(void* const* d_in, const int* in_sizes, int n_in,
                              void* d_out, int out_size)
{
    const float* x       = (const float*)d_in[0];
    const int*   eidx    = (const int*)  d_in[1];
    const float* eattr   = (const float*)d_in[2];
    const float* gfeat   = (const float*)d_in[3];
    const float* W_rel1  = (const float*)d_in[4];
    const float* b1      = (const float*)d_in[5];
    const float* W_root1 = (const float*)d_in[6];
    const float* W_rel2  = (const float*)d_in[7];
    const float* b2      = (const float*)d_in[8];
    const float* W_root2 = (const float*)d_in[9];
    const float* Wg1     = (const float*)d_in[10];
    const float* bg1     = (const float*)d_in[11];
    const float* Wg2     = (const float*)d_in[12];
    const float* bg2     = (const float*)d_in[13];
    const float* Wg3     = (const float*)d_in[14];
    const float* bg3     = (const float*)d_in[15];
    const float* Wo1     = (const float*)d_in[16];
    const float* bo1     = (const float*)d_in[17];
    const float* Wo2     = (const float*)d_in[18];
    const float* bo2     = (const float*)d_in[19];
    float* out = (float*)d_out;

    gconv_kernel<<<BGR / WPG, 128>>>(x, eidx, eattr, gfeat,
                                     W_rel1, b1, W_root1,
                                     W_rel2, b2, W_root2,
                                     Wg1, bg1, Wg2, bg2, Wg3, bg3);
    head_kernel<<<BGR / BM, 128>>>(Wo1, bo1, Wo2, bo2, out);
}